// round 2
// baseline (speedup 1.0000x reference)
#include <cuda_runtime.h>
#include <cstdint>

#define DD   128
#define TT   4
#define NMAX 25000
#define HPAD 129

// Scratch for per-atom precomputed layer-0 partials: E[a][n][j]
__device__ float g_E[4L * NMAX * DD];  // 51.2 MB
__device__ int   g_idx64;              // 1 if propers buffer is int64, else int32

// ---------------------------------------------------------------------------
// Detect index dtype: for int64 little-endian values in [0, 25000) every odd
// 32-bit word is zero. For int32 data that's (1/25000)^~2048 — impossible.
// ---------------------------------------------------------------------------
__global__ void detect_idx_kernel(const int* __restrict__ words, int nwords)
{
    __shared__ int nz;
    if (threadIdx.x == 0) nz = 0;
    __syncthreads();
    for (int i = 1 + 2 * threadIdx.x; i < nwords; i += 2 * blockDim.x) {
        if (words[i] != 0) { atomicOr(&nz, 1); break; }
    }
    __syncthreads();
    if (threadIdx.x == 0) g_idx64 = (nz == 0) ? 1 : 0;
}

// ---------------------------------------------------------------------------
// Kernel A: E[a][n][j] = sum_k enc[n][k] * W0[(a*128+k)*128 + j]
// grid = (ceil(N/64), 4), block = 256
// ---------------------------------------------------------------------------
__global__ void __launch_bounds__(256) precompute_E_kernel(
    const float* __restrict__ enc,
    const float* __restrict__ W0,
    int N)
{
    extern __shared__ float sm[];
    float* sW = sm;               // 128*128
    float* sE = sm + DD * DD;     // 64 * HPAD

    const int a    = blockIdx.y;
    const int tile = blockIdx.x;
    const int tid  = threadIdx.x;

    {
        const float4* src = (const float4*)(W0 + (size_t)(a * 128) * DD);
        float4* dst = (float4*)sW;
        for (int i = tid; i < DD * DD / 4; i += 256) dst[i] = src[i];
    }
    for (int i = tid; i < 64 * DD / 4; i += 256) {
        int r  = i / (DD / 4);
        int kc = (i % (DD / 4)) * 4;
        int atom = tile * 64 + r;
        float4 v = make_float4(0.f, 0.f, 0.f, 0.f);
        if (atom < N) v = *(const float4*)(enc + (size_t)atom * DD + kc);
        sE[r * HPAD + kc + 0] = v.x;
        sE[r * HPAD + kc + 1] = v.y;
        sE[r * HPAD + kc + 2] = v.z;
        sE[r * HPAD + kc + 3] = v.w;
    }
    __syncthreads();

    const int tc = tid & 15;
    const int tr = tid >> 4;

    float acc[4][8];
    #pragma unroll
    for (int i = 0; i < 4; i++)
        #pragma unroll
        for (int j = 0; j < 8; j++) acc[i][j] = 0.f;

    #pragma unroll 4
    for (int k = 0; k < DD; k++) {
        float av[4];
        #pragma unroll
        for (int i = 0; i < 4; i++) av[i] = sE[(tr * 4 + i) * HPAD + k];
        float4 bA = *(const float4*)&sW[k * DD + tc * 8];
        float4 bB = *(const float4*)&sW[k * DD + tc * 8 + 4];
        #pragma unroll
        for (int i = 0; i < 4; i++) {
            acc[i][0] += av[i] * bA.x; acc[i][1] += av[i] * bA.y;
            acc[i][2] += av[i] * bA.z; acc[i][3] += av[i] * bA.w;
            acc[i][4] += av[i] * bB.x; acc[i][5] += av[i] * bB.y;
            acc[i][6] += av[i] * bB.z; acc[i][7] += av[i] * bB.w;
        }
    }

    #pragma unroll
    for (int i = 0; i < 4; i++) {
        int atom = tile * 64 + tr * 4 + i;
        if (atom < N) {
            float* dst = g_E + ((size_t)a * N + atom) * DD + tc * 8;
            *(float4*)(dst + 0) = make_float4(acc[i][0], acc[i][1], acc[i][2], acc[i][3]);
            *(float4*)(dst + 4) = make_float4(acc[i][4], acc[i][5], acc[i][6], acc[i][7]);
        }
    }
}

// ---------------------------------------------------------------------------
// Fused MLP layer: sh (128 rows x 128, pad HPAD) = leaky(sh @ Wsm + bvec)
// ---------------------------------------------------------------------------
__device__ __forceinline__ void mlp_layer(float* __restrict__ sh,
                                          const float* __restrict__ Wsm,
                                          const float* __restrict__ bvec,
                                          int tid)
{
    const int tc = tid & 15;
    const int tr = tid >> 4;

    float acc[8][8];
    #pragma unroll
    for (int i = 0; i < 8; i++)
        #pragma unroll
        for (int j = 0; j < 8; j++) acc[i][j] = bvec[tc * 8 + j];

    #pragma unroll 4
    for (int k = 0; k < DD; k++) {
        float av[8];
        #pragma unroll
        for (int i = 0; i < 8; i++) av[i] = sh[(tr * 8 + i) * HPAD + k];
        float4 bA = *(const float4*)&Wsm[k * DD + tc * 8];
        float4 bB = *(const float4*)&Wsm[k * DD + tc * 8 + 4];
        #pragma unroll
        for (int i = 0; i < 8; i++) {
            acc[i][0] += av[i] * bA.x; acc[i][1] += av[i] * bA.y;
            acc[i][2] += av[i] * bA.z; acc[i][3] += av[i] * bA.w;
            acc[i][4] += av[i] * bB.x; acc[i][5] += av[i] * bB.y;
            acc[i][6] += av[i] * bB.z; acc[i][7] += av[i] * bB.w;
        }
    }
    __syncthreads();
    #pragma unroll
    for (int i = 0; i < 8; i++)
        #pragma unroll
        for (int j = 0; j < 8; j++) {
            float v = acc[i][j];
            v = (v > 0.f) ? v : 0.001f * v;
            sh[(tr * 8 + i) * HPAD + tc * 8 + j] = v;
        }
    __syncthreads();
}

// ---------------------------------------------------------------------------
// Kernel C: per block = 32 propers (128 rows of (p,t)).
// ---------------------------------------------------------------------------
__global__ void __launch_bounds__(256) propers_kernel(
    const float* __restrict__ coords,
    const void* __restrict__ propers_raw,
    const float* __restrict__ t_arr,
    const float* __restrict__ W0,
    const float* __restrict__ b0,
    const float* __restrict__ W1,
    const float* __restrict__ b1,
    const float* __restrict__ W2,
    const float* __restrict__ b2,
    const float* __restrict__ W3,
    const float* __restrict__ b3,
    float* __restrict__ out,
    int N, int P)
{
    extern __shared__ float sm[];
    float* sW1    = sm;                         // 16384
    float* sW2    = sW1 + DD * DD;              // 16384
    float* sh     = sW2 + DD * DD;              // 128*HPAD
    float* sW3    = sh + 128 * HPAD;            // 256
    float* vwt    = sW3 + 256;                  // 128
    float* vws    = vwt + DD;
    float* vwc    = vws + DD;
    float* vwd    = vwc + DD;
    float* vb0    = vwd + DD;
    float* vb1    = vb0 + DD;
    float* vb2    = vb1 + DD;
    float* vb3    = vb2 + DD;                   // 4
    float* stv    = vb3 + 4;                    // 4
    float* ssin   = stv + 4;                    // 128
    float* scos   = ssin + 128;                 // 128
    float* sdl    = scos + 128;                 // 128
    float* sdh    = sdl + 128;                  // 384
    float* sdelta = sdh + 384;                  // 256
    int*   sprop  = (int*)(sdelta + 256);       // 128

    const int tid   = threadIdx.x;
    const int pbase = blockIdx.x * 32;
    const int is64  = g_idx64;

    // ---- phase 0: load weights / biases / indices ----
    {
        const float4* s1 = (const float4*)W1;
        const float4* s2 = (const float4*)W2;
        float4* d1 = (float4*)sW1;
        float4* d2 = (float4*)sW2;
        for (int i = tid; i < DD * DD / 4; i += 256) { d1[i] = s1[i]; d2[i] = s2[i]; }
    }
    if (tid < 128) {
        vwt[tid] = W0[(size_t)512 * DD + tid];
        vws[tid] = W0[(size_t)513 * DD + tid];
        vwc[tid] = W0[(size_t)514 * DD + tid];
        vwd[tid] = W0[(size_t)515 * DD + tid];
        vb0[tid] = b0[tid];
        vb1[tid] = b1[tid];
        vb2[tid] = b2[tid];
        // proper indices: 32 propers x 4, clamped to [0, N)
        int p = pbase + (tid >> 2);
        long long idx = 0;
        if (p < P) {
            size_t off = (size_t)p * 4 + (tid & 3);
            idx = is64 ? ((const long long*)propers_raw)[off]
                       : (long long)((const int*)propers_raw)[off];
        }
        if (idx < 0) idx = 0;
        if (idx >= N) idx = N - 1;
        sprop[tid] = (int)idx;
    }
    sW3[tid & 255] = W3[tid & 255];
    if (tid < 2)  vb3[tid] = b3[tid];
    if (tid < TT) stv[tid] = t_arr[tid];
    __syncthreads();

    // ---- phase 1a: geometry per row ----
    if (tid < 128) {
        const int row = tid;
        const int lp  = row >> 2;
        const int tt  = row & 3;
        const int i0 = sprop[lp * 4 + 0];
        const int i1 = sprop[lp * 4 + 1];
        const int i2 = sprop[lp * 4 + 2];
        const int i3 = sprop[lp * 4 + 3];

        const float* c0 = coords + (size_t)(i0 * TT + tt) * 3;
        const float* c1 = coords + (size_t)(i1 * TT + tt) * 3;
        const float* c2 = coords + (size_t)(i2 * TT + tt) * 3;
        const float* c3 = coords + (size_t)(i3 * TT + tt) * 3;

        float c0x = c0[0], c0y = c0[1], c0z = c0[2];
        float c1x = c1[0], c1y = c1[1], c1z = c1[2];
        float c2x = c2[0], c2y = c2[1], c2z = c2[2];
        float c3x = c3[0], c3y = c3[1], c3z = c3[2];

        float u1x = c1x - c0x, u1y = c1y - c0y, u1z = c1z - c0z;
        float u2x = c2x - c1x, u2y = c2y - c1y, u2z = c2z - c1z;
        float u3x = c3x - c2x, u3y = c3y - c2y, u3z = c3z - c2z;

        float ax = u1y * u2z - u1z * u2y;
        float ay = u1z * u2x - u1x * u2z;
        float az = u1x * u2y - u1y * u2x;
        float bx = u2y * u3z - u2z * u3y;
        float by = u2z * u3x - u2x * u3z;
        float bz = u2x * u3y - u2y * u3x;

        float x   = ax * bx + ay * by + az * bz;
        float u2n = sqrtf(u2x * u2x + u2y * u2y + u2z * u2z);
        float y   = u2n * (u1x * bx + u1y * by + u1z * bz);

        float r2 = x * x + y * y;
        float s, c;
        if (r2 > 1e-30f) {
            float rinv = rsqrtf(r2);
            s = y * rinv;
            c = x * rinv;
        } else { s = 0.f; c = 1.f; }

        float drx = c0x - c3x, dry = c0y - c3y, drz = c0z - c3z;
        float dl  = sqrtf(fmaxf(drx * drx + dry * dry + drz * drz, 1e-12f));
        float inv = 1.f / dl;

        ssin[row] = s;
        scos[row] = c;
        sdl[row]  = dl;
        sdh[row * 3 + 0] = drx * inv;
        sdh[row * 3 + 1] = dry * inv;
        sdh[row * 3 + 2] = drz * inv;
    }
    __syncthreads();

    // ---- phase 1b: h0 = leaky(gathered E sums + scalar features) ----
    {
        const int lp = tid >> 3;       // 32 propers
        const int u  = tid & 7;        // 8 col-chunks of 16
        const int i0 = sprop[lp * 4 + 0];
        const int i1 = sprop[lp * 4 + 1];
        const int i2 = sprop[lp * 4 + 2];
        const int i3 = sprop[lp * 4 + 3];
        const float* E0 = g_E + (size_t)i0 * DD;
        const float* E1 = g_E + ((size_t)N * 1 + i1) * DD;
        const float* E2 = g_E + ((size_t)N * 2 + i2) * DD;
        const float* E3 = g_E + ((size_t)N * 3 + i3) * DD;

        #pragma unroll
        for (int m = 0; m < 4; m++) {
            const int col = u * 16 + m * 4;
            float4 e0 = *(const float4*)(E0 + col);
            float4 e1 = *(const float4*)(E1 + col);
            float4 e2 = *(const float4*)(E2 + col);
            float4 e3 = *(const float4*)(E3 + col);
            float4 bb = *(const float4*)(vb0 + col);
            float bxv = e0.x + e1.x + e2.x + e3.x + bb.x;
            float byv = e0.y + e1.y + e2.y + e3.y + bb.y;
            float bzv = e0.z + e1.z + e2.z + e3.z + bb.z;
            float bwv = e0.w + e1.w + e2.w + e3.w + bb.w;
            float4 vt = *(const float4*)(vwt + col);
            float4 vs = *(const float4*)(vws + col);
            float4 vc = *(const float4*)(vwc + col);
            float4 vd = *(const float4*)(vwd + col);
            #pragma unroll
            for (int tt = 0; tt < TT; tt++) {
                const int row = lp * 4 + tt;
                float tv = stv[tt];
                float sv = ssin[row];
                float cv = scos[row];
                float dv = sdl[row];
                float vx = bxv + tv * vt.x + sv * vs.x + cv * vc.x + dv * vd.x;
                float vy = byv + tv * vt.y + sv * vs.y + cv * vc.y + dv * vd.y;
                float vz = bzv + tv * vt.z + sv * vs.z + cv * vc.z + dv * vd.z;
                float vw = bwv + tv * vt.w + sv * vs.w + cv * vc.w + dv * vd.w;
                vx = (vx > 0.f) ? vx : 0.001f * vx;
                vy = (vy > 0.f) ? vy : 0.001f * vy;
                vz = (vz > 0.f) ? vz : 0.001f * vz;
                vw = (vw > 0.f) ? vw : 0.001f * vw;
                float* dst = sh + row * HPAD + col;
                dst[0] = vx; dst[1] = vy; dst[2] = vz; dst[3] = vw;
            }
        }
    }
    __syncthreads();

    // ---- phases 2,3: two 128x128 layers ----
    mlp_layer(sh, sW1, vb1, tid);
    mlp_layer(sh, sW2, vb2, tid);

    // ---- phase 4: delta = sh @ W3 + b3 (128 rows x 2) ----
    {
        const int row = tid >> 1;
        const int col = tid & 1;
        float acc = vb3[col];
        const float* hrow = sh + row * HPAD;
        #pragma unroll 8
        for (int k = 0; k < DD; k++) acc += hrow[k] * sW3[k * 2 + col];
        sdelta[row * 2 + col] = acc;
    }
    __syncthreads();

    // ---- phase 5: scatter atomics ----
    if (tid < 128) {
        const int row = tid;
        const int lp  = row >> 2;
        const int tt  = row & 3;
        const int p   = pbase + lp;
        if (p < P) {
            const int i0 = sprop[lp * 4 + 0];
            const int i3 = sprop[lp * 4 + 3];
            float d0 = sdelta[row * 2 + 0];
            float d1 = sdelta[row * 2 + 1];
            float hx = sdh[row * 3 + 0];
            float hy = sdh[row * 3 + 1];
            float hz = sdh[row * 3 + 2];
            float* o0 = out + (size_t)(i0 * TT + tt) * 3;
            float* o3 = out + (size_t)(i3 * TT + tt) * 3;
            atomicAdd(o0 + 0, -0.5f * d0 * hx);
            atomicAdd(o0 + 1, -0.5f * d0 * hy);
            atomicAdd(o0 + 2, -0.5f * d0 * hz);
            atomicAdd(o3 + 0,  0.5f * d1 * hx);
            atomicAdd(o3 + 1,  0.5f * d1 * hy);
            atomicAdd(o3 + 2,  0.5f * d1 * hz);
        }
    }
}

// ---------------------------------------------------------------------------
extern "C" void kernel_launch(void* const* d_in, const int* in_sizes, int n_in,
                              void* d_out, int out_size)
{
    const float* coords  = (const float*)d_in[0];
    const void*  propers = d_in[1];
    const float* enc     = (const float*)d_in[2];
    const float* t_arr   = (const float*)d_in[3];
    const float* answer  = (const float*)d_in[4];
    const float* W0      = (const float*)d_in[5];
    const float* b0      = (const float*)d_in[6];
    const float* W1      = (const float*)d_in[7];
    const float* b1      = (const float*)d_in[8];
    const float* W2      = (const float*)d_in[9];
    const float* b2      = (const float*)d_in[10];
    const float* W3      = (const float*)d_in[11];
    const float* b3      = (const float*)d_in[12];
    float*       out     = (float*)d_out;

    const int N = in_sizes[2] / DD;
    const int P = in_sizes[1] / 4;

    // detect propers dtype (int32 vs int64) on device
    int nwords = in_sizes[1] < 4096 ? in_sizes[1] : 4096;
    detect_idx_kernel<<<1, 256>>>((const int*)propers, nwords);

    // out starts as 'answer'
    cudaMemcpyAsync(out, answer, sizeof(float) * (size_t)in_sizes[4],
                    cudaMemcpyDeviceToDevice, 0);

    // kernel A: per-atom layer-0 partials
    const size_t smA = (size_t)(DD * DD + 64 * HPAD) * sizeof(float);
    cudaFuncSetAttribute(precompute_E_kernel,
                         cudaFuncAttributeMaxDynamicSharedMemorySize, (int)smA);
    precompute_E_kernel<<<dim3((N + 63) / 64, 4), 256, smA>>>(enc, W0, N);

    // kernel C: fused geometry + MLP + scatter
    const size_t smC = (size_t)(2 * DD * DD + 128 * HPAD + 256 + 8 * DD + 8
                                + 3 * 128 + 384 + 256 + 128) * sizeof(float);
    cudaFuncSetAttribute(propers_kernel,
                         cudaFuncAttributeMaxDynamicSharedMemorySize, (int)smC);
    propers_kernel<<<(P + 31) / 32, 256, smC>>>(
        coords, propers, t_arr, W0, b0, W1, b1, W2, b2, W3, b3, out, N, P);
}

// round 4
// speedup vs baseline: 1.8582x; 1.8582x over previous
#include <cuda_runtime.h>
#include <cuda_bf16.h>
#include <cstdint>

#define DD   128
#define TT   4
#define NMAX 25000
#define HPAD 129

// ---------------------------------------------------------------------------
// Global scratch
// ---------------------------------------------------------------------------
__device__ float g_E[4L * NMAX * DD];   // per-atom layer-0 partials (51.2 MB)
__device__ int   g_idx64;               // propers dtype flag
// Weight images: [img 0..3][n 0..127][k padded to 136 bf16]
//   img = layer*2 + (0=hi, 1=lo);  bf16, B^T layout (n-major, k contiguous)
#define PITCH_B   272                   // 136 bf16 * 2 bytes
#define IMG_BYTES 34816                 // 128 * 272
__device__ __align__(16) unsigned char g_Bimg[4 * IMG_BYTES];

// ---------------------------------------------------------------------------
// helpers
// ---------------------------------------------------------------------------
__device__ __forceinline__ uint32_t pack_split(float v0, float v1, uint32_t& lo_out) {
    __nv_bfloat16 h0 = __float2bfloat16_rn(v0);
    __nv_bfloat16 h1 = __float2bfloat16_rn(v1);
    float r0 = v0 - __bfloat162float(h0);
    float r1 = v1 - __bfloat162float(h1);
    __nv_bfloat16 l0 = __float2bfloat16_rn(r0);
    __nv_bfloat16 l1 = __float2bfloat16_rn(r1);
    lo_out = (uint32_t)__bfloat16_as_ushort(l0) | ((uint32_t)__bfloat16_as_ushort(l1) << 16);
    return (uint32_t)__bfloat16_as_ushort(h0) | ((uint32_t)__bfloat16_as_ushort(h1) << 16);
}

__device__ __forceinline__ void mma16816(float d[4], const uint32_t a[4], const uint32_t b[2]) {
    asm volatile(
        "mma.sync.aligned.m16n8k16.row.col.f32.bf16.bf16.f32 "
        "{%0,%1,%2,%3}, {%4,%5,%6,%7}, {%8,%9}, {%0,%1,%2,%3};"
        : "+f"(d[0]), "+f"(d[1]), "+f"(d[2]), "+f"(d[3])
        : "r"(a[0]), "r"(a[1]), "r"(a[2]), "r"(a[3]), "r"(b[0]), "r"(b[1]));
}

// ---------------------------------------------------------------------------
// detect propers dtype (int64 little-endian small values -> odd words all 0)
// ---------------------------------------------------------------------------
__global__ void detect_idx_kernel(const int* __restrict__ words, int nwords)
{
    __shared__ int nz;
    if (threadIdx.x == 0) nz = 0;
    __syncthreads();
    for (int i = 1 + 2 * threadIdx.x; i < nwords; i += 2 * blockDim.x) {
        if (words[i] != 0) { atomicOr(&nz, 1); break; }
    }
    __syncthreads();
    if (threadIdx.x == 0) g_idx64 = (nz == 0) ? 1 : 0;
}

// ---------------------------------------------------------------------------
// prep: build bf16 hi/lo B^T images of W1 and W2 (padded pitch)
// ---------------------------------------------------------------------------
__global__ void prep_B_kernel(const float* __restrict__ W1,
                              const float* __restrict__ W2)
{
    int idx = blockIdx.x * blockDim.x + threadIdx.x;
    if (idx >= 2 * 128 * 64) return;
    int l = idx >> 13;
    int r = idx & 8191;
    int n = r >> 6;
    int k = (r & 63) * 2;
    const float* W = l ? W2 : W1;
    float v0 = W[(size_t)k * DD + n];
    float v1 = W[(size_t)(k + 1) * DD + n];
    uint32_t lo, hi = pack_split(v0, v1, lo);
    uint32_t off = (uint32_t)n * PITCH_B + (uint32_t)k * 2;
    *(uint32_t*)(g_Bimg + (l * 2 + 0) * IMG_BYTES + off) = hi;
    *(uint32_t*)(g_Bimg + (l * 2 + 1) * IMG_BYTES + off) = lo;
}

// ---------------------------------------------------------------------------
// Kernel A: E[a][n][j] = sum_k enc[n][k] * W0[(a*128+k)*128 + j]   (fp32)
// ---------------------------------------------------------------------------
__global__ void __launch_bounds__(256) precompute_E_kernel(
    const float* __restrict__ enc,
    const float* __restrict__ W0,
    int N)
{
    extern __shared__ float sm[];
    float* sW = sm;
    float* sE = sm + DD * DD;

    const int a    = blockIdx.y;
    const int tile = blockIdx.x;
    const int tid  = threadIdx.x;

    {
        const float4* src = (const float4*)(W0 + (size_t)(a * 128) * DD);
        float4* dst = (float4*)sW;
        for (int i = tid; i < DD * DD / 4; i += 256) dst[i] = src[i];
    }
    for (int i = tid; i < 64 * DD / 4; i += 256) {
        int r  = i / (DD / 4);
        int kc = (i % (DD / 4)) * 4;
        int atom = tile * 64 + r;
        float4 v = make_float4(0.f, 0.f, 0.f, 0.f);
        if (atom < N) v = *(const float4*)(enc + (size_t)atom * DD + kc);
        sE[r * HPAD + kc + 0] = v.x;
        sE[r * HPAD + kc + 1] = v.y;
        sE[r * HPAD + kc + 2] = v.z;
        sE[r * HPAD + kc + 3] = v.w;
    }
    __syncthreads();

    const int tc = tid & 15;
    const int tr = tid >> 4;

    float acc[4][8];
    #pragma unroll
    for (int i = 0; i < 4; i++)
        #pragma unroll
        for (int j = 0; j < 8; j++) acc[i][j] = 0.f;

    #pragma unroll 4
    for (int k = 0; k < DD; k++) {
        float av[4];
        #pragma unroll
        for (int i = 0; i < 4; i++) av[i] = sE[(tr * 4 + i) * HPAD + k];
        float4 bA = *(const float4*)&sW[k * DD + tc * 8];
        float4 bB = *(const float4*)&sW[k * DD + tc * 8 + 4];
        #pragma unroll
        for (int i = 0; i < 4; i++) {
            acc[i][0] += av[i] * bA.x; acc[i][1] += av[i] * bA.y;
            acc[i][2] += av[i] * bA.z; acc[i][3] += av[i] * bA.w;
            acc[i][4] += av[i] * bB.x; acc[i][5] += av[i] * bB.y;
            acc[i][6] += av[i] * bB.z; acc[i][7] += av[i] * bB.w;
        }
    }

    #pragma unroll
    for (int i = 0; i < 4; i++) {
        int atom = tile * 64 + tr * 4 + i;
        if (atom < N) {
            float* dst = g_E + ((size_t)a * N + atom) * DD + tc * 8;
            *(float4*)(dst + 0) = make_float4(acc[i][0], acc[i][1], acc[i][2], acc[i][3]);
            *(float4*)(dst + 4) = make_float4(acc[i][4], acc[i][5], acc[i][6], acc[i][7]);
        }
    }
}

// ---------------------------------------------------------------------------
// Main fused kernel.
// 256 threads = 8 warps. Per tile: 32 propers = 128 rows.
// Warp w owns rows [w*16, w*16+16): layer0 writes, both MMAs, epilogues are
// warp-private on A -> only 2 __syncthreads per tile.
// ---------------------------------------------------------------------------
#define A_HI     0
#define A_LO     IMG_BYTES                 // 34816
#define W_SM     (2 * IMG_BYTES)           // 69632
#define MISC_OFF (W_SM + 4 * IMG_BYTES)    // 208896
#define SMEM_TOTAL (MISC_OFF + 2056 * 4)   // 217120
#define TILES_PER_BLOCK 4

__global__ void __launch_bounds__(256, 1) propers_kernel(
    const float* __restrict__ coords,
    const void* __restrict__ propers_raw,
    const float* __restrict__ t_arr,
    const float* __restrict__ W0,
    const float* __restrict__ b0,
    const float* __restrict__ b1,
    const float* __restrict__ b2,
    const float* __restrict__ W3,
    const float* __restrict__ b3,
    float* __restrict__ out,
    int N, int P)
{
    extern __shared__ char smem_raw[];

    float* m    = (float*)(smem_raw + MISC_OFF);
    float* vb1  = m;                // 128
    float* vb2  = m + 128;          // 128
    float* vwt  = m + 256;          // 128
    float* vws  = m + 384;
    float* vwc  = m + 512;
    float* vwd  = m + 640;
    float* vb0  = m + 768;
    float* sW3  = m + 896;          // 256
    float* vb3  = m + 1152;         // 2 (+2 pad)
    float* stv  = m + 1156;         // 4
    float* ssin = m + 1160;         // 128
    float* scos = m + 1288;
    float* sdl  = m + 1416;
    float* sdh  = m + 1544;         // 384
    int*   sprop= (int*)(m + 1928); // 128

    const int tid  = threadIdx.x;
    const int w    = tid >> 5;
    const int t    = tid & 31;
    const int is64 = g_idx64;

    // ---- one-time: weights + small vectors ----
    {
        const float4* src = (const float4*)g_Bimg;
        float4* dst = (float4*)(smem_raw + W_SM);
        for (int i = tid; i < 4 * IMG_BYTES / 16; i += 256) dst[i] = src[i];
    }
    if (tid < 128) {
        vwt[tid] = W0[(size_t)512 * DD + tid];
        vws[tid] = W0[(size_t)513 * DD + tid];
        vwc[tid] = W0[(size_t)514 * DD + tid];
        vwd[tid] = W0[(size_t)515 * DD + tid];
        vb0[tid] = b0[tid];
        vb1[tid] = b1[tid];
        vb2[tid] = b2[tid];
    } else {
        int i = tid - 128;
        if (i < 2)  vb3[i] = b3[i];
        if (i < TT) stv[i] = t_arr[i];
    }
    for (int i = tid; i < 256; i += 256) sW3[i] = W3[i];
    __syncthreads();

    // per-thread fragment geometry
    const int row0 = w * 16 + (t >> 2);    // A/D row (second row = +8)
    const int qk4  = (t & 3) * 4;          // byte offset of k-quad within kstep

    for (int tile = 0; tile < TILES_PER_BLOCK; tile++) {
        const int pbase = blockIdx.x * (32 * TILES_PER_BLOCK) + tile * 32;

        // ---- indices (warp-local w.r.t. geometry below) ----
        if (tid < 128) {
            int p = pbase + (tid >> 2);
            long long idx = 0;
            if (p < P) {
                size_t off = (size_t)p * 4 + (tid & 3);
                idx = is64 ? ((const long long*)propers_raw)[off]
                           : (long long)((const int*)propers_raw)[off];
            }
            if (idx < 0) idx = 0;
            if (idx >= N) idx = N - 1;
            sprop[tid] = (int)idx;
        }
        __syncwarp();

        // ---- geometry per row (reads warp-local sprop) ----
        if (tid < 128) {
            const int row = tid;
            const int lp  = row >> 2;
            const int tt  = row & 3;
            const int i0 = sprop[lp * 4 + 0];
            const int i1 = sprop[lp * 4 + 1];
            const int i2 = sprop[lp * 4 + 2];
            const int i3 = sprop[lp * 4 + 3];

            const float* c0 = coords + (size_t)(i0 * TT + tt) * 3;
            const float* c1 = coords + (size_t)(i1 * TT + tt) * 3;
            const float* c2 = coords + (size_t)(i2 * TT + tt) * 3;
            const float* c3 = coords + (size_t)(i3 * TT + tt) * 3;

            float c0x = c0[0], c0y = c0[1], c0z = c0[2];
            float c1x = c1[0], c1y = c1[1], c1z = c1[2];
            float c2x = c2[0], c2y = c2[1], c2z = c2[2];
            float c3x = c3[0], c3y = c3[1], c3z = c3[2];

            float u1x = c1x - c0x, u1y = c1y - c0y, u1z = c1z - c0z;
            float u2x = c2x - c1x, u2y = c2y - c1y, u2z = c2z - c1z;
            float u3x = c3x - c2x, u3y = c3y - c2y, u3z = c3z - c2z;

            float ax = u1y * u2z - u1z * u2y;
            float ay = u1z * u2x - u1x * u2z;
            float az = u1x * u2y - u1y * u2x;
            float bx = u2y * u3z - u2z * u3y;
            float by = u2z * u3x - u2x * u3z;
            float bz = u2x * u3y - u2y * u3x;

            float x   = ax * bx + ay * by + az * bz;
            float u2n = sqrtf(u2x * u2x + u2y * u2y + u2z * u2z);
            float y   = u2n * (u1x * bx + u1y * by + u1z * bz);

            float r2 = x * x + y * y;
            float s, c;
            if (r2 > 1e-30f) {
                float rinv = rsqrtf(r2);
                s = y * rinv;
                c = x * rinv;
            } else { s = 0.f; c = 1.f; }

            float drx = c0x - c3x, dry = c0y - c3y, drz = c0z - c3z;
            float dl  = sqrtf(fmaxf(drx * drx + dry * dry + drz * drz, 1e-12f));
            float inv = 1.f / dl;

            ssin[row] = s;
            scos[row] = c;
            sdl[row]  = dl;
            sdh[row * 3 + 0] = drx * inv;
            sdh[row * 3 + 1] = dry * inv;
            sdh[row * 3 + 2] = drz * inv;
        }
        __syncthreads();   // geometry visible to all warps

        // ---- layer 0: gathered E sums + scalar feats -> split bf16 A tile ----
        // thread handles proper lp = tid>>3 (rows lp*4..lp*4+3: warp-private!)
        {
            const int lp = tid >> 3;
            const int u  = tid & 7;
            const int i0 = sprop[lp * 4 + 0];
            const int i1 = sprop[lp * 4 + 1];
            const int i2 = sprop[lp * 4 + 2];
            const int i3 = sprop[lp * 4 + 3];
            const float* E0 = g_E + (size_t)i0 * DD;
            const float* E1 = g_E + ((size_t)N * 1 + i1) * DD;
            const float* E2 = g_E + ((size_t)N * 2 + i2) * DD;
            const float* E3 = g_E + ((size_t)N * 3 + i3) * DD;

            #pragma unroll
            for (int mm = 0; mm < 4; mm++) {
                const int col = u * 16 + mm * 4;
                float4 e0 = *(const float4*)(E0 + col);
                float4 e1 = *(const float4*)(E1 + col);
                float4 e2 = *(const float4*)(E2 + col);
                float4 e3 = *(const float4*)(E3 + col);
                float4 bb = *(const float4*)(vb0 + col);
                float bxv = e0.x + e1.x + e2.x + e3.x + bb.x;
                float byv = e0.y + e1.y + e2.y + e3.y + bb.y;
                float bzv = e0.z + e1.z + e2.z + e3.z + bb.z;
                float bwv = e0.w + e1.w + e2.w + e3.w + bb.w;
                float4 vt = *(const float4*)(vwt + col);
                float4 vs = *(const float4*)(vws + col);
                float4 vc = *(const float4*)(vwc + col);
                float4 vd = *(const float4*)(vwd + col);
                #pragma unroll
                for (int tt = 0; tt < TT; tt++) {
                    const int row = lp * 4 + tt;
                    float tv = stv[tt];
                    float sv = ssin[row];
                    float cv = scos[row];
                    float dv = sdl[row];
                    float vx = bxv + tv * vt.x + sv * vs.x + cv * vc.x + dv * vd.x;
                    float vy = byv + tv * vt.y + sv * vs.y + cv * vc.y + dv * vd.y;
                    float vz = bzv + tv * vt.z + sv * vs.z + cv * vc.z + dv * vd.z;
                    float vw = bwv + tv * vt.w + sv * vs.w + cv * vc.w + dv * vd.w;
                    vx = (vx > 0.f) ? vx : 0.001f * vx;
                    vy = (vy > 0.f) ? vy : 0.001f * vy;
                    vz = (vz > 0.f) ? vz : 0.001f * vz;
                    vw = (vw > 0.f) ? vw : 0.001f * vw;
                    uint32_t lo0, hi0 = pack_split(vx, vy, lo0);
                    uint32_t lo1, hi1 = pack_split(vz, vw, lo1);
                    uint32_t o = (uint32_t)row * PITCH_B + (uint32_t)col * 2;
                    *(uint32_t*)(smem_raw + A_HI + o)     = hi0;
                    *(uint32_t*)(smem_raw + A_HI + o + 4) = hi1;
                    *(uint32_t*)(smem_raw + A_LO + o)     = lo0;
                    *(uint32_t*)(smem_raw + A_LO + o + 4) = lo1;
                }
            }
        }
        __syncwarp();  // A rows warp-private; just order within warp

        // ================= layer 1 (W1) =================
        float D[16][4];
        #pragma unroll
        for (int nt = 0; nt < 16; nt++)
            #pragma unroll
            for (int j = 0; j < 4; j++) D[nt][j] = 0.f;

        {
            const char* Ah = smem_raw + A_HI;
            const char* Al = smem_raw + A_LO;
            const char* Bh = smem_raw + W_SM + 0 * IMG_BYTES;
            const char* Bl = smem_raw + W_SM + 1 * IMG_BYTES;
            const int nrow = (t >> 2);
            #pragma unroll
            for (int ks = 0; ks < 8; ks++) {
                const int kb = ks * 32 + qk4;
                uint32_t ah[4], al[4];
                ah[0] = *(const uint32_t*)(Ah + row0 * PITCH_B + kb);
                ah[1] = *(const uint32_t*)(Ah + (row0 + 8) * PITCH_B + kb);
                ah[2] = *(const uint32_t*)(Ah + row0 * PITCH_B + kb + 16);
                ah[3] = *(const uint32_t*)(Ah + (row0 + 8) * PITCH_B + kb + 16);
                al[0] = *(const uint32_t*)(Al + row0 * PITCH_B + kb);
                al[1] = *(const uint32_t*)(Al + (row0 + 8) * PITCH_B + kb);
                al[2] = *(const uint32_t*)(Al + row0 * PITCH_B + kb + 16);
                al[3] = *(const uint32_t*)(Al + (row0 + 8) * PITCH_B + kb + 16);
                #pragma unroll
                for (int nt = 0; nt < 16; nt++) {
                    const int n = nt * 8 + nrow;
                    uint32_t bh[2], bl[2];
                    bh[0] = *(const uint32_t*)(Bh + n * PITCH_B + kb);
                    bh[1] = *(const uint32_t*)(Bh + n * PITCH_B + kb + 16);
                    bl[0] = *(const uint32_t*)(Bl + n * PITCH_B + kb);
                    bl[1] = *(const uint32_t*)(Bl + n * PITCH_B + kb + 16);
                    mma16816(D[nt], ah, bh);
                    mma16816(D[nt], ah, bl);
                    mma16816(D[nt], al, bh);
                }
            }
        }

        // ---- epilogue 1: bias + leaky, re-split into A tile (warp-private) ----
        {
            #pragma unroll
            for (int nt = 0; nt < 16; nt++) {
                const int c0 = nt * 8 + (t & 3) * 2;
                float bia = vb1[c0], bib = vb1[c0 + 1];
                float v0 = D[nt][0] + bia, v1 = D[nt][1] + bib;
                float v2 = D[nt][2] + bia, v3 = D[nt][3] + bib;
                v0 = (v0 > 0.f) ? v0 : 0.001f * v0;
                v1 = (v1 > 0.f) ? v1 : 0.001f * v1;
                v2 = (v2 > 0.f) ? v2 : 0.001f * v2;
                v3 = (v3 > 0.f) ? v3 : 0.001f * v3;
                uint32_t lo0, hi0 = pack_split(v0, v1, lo0);
                uint32_t lo1, hi1 = pack_split(v2, v3, lo1);
                uint32_t oA = (uint32_t)row0 * PITCH_B + (uint32_t)c0 * 2;
                uint32_t oB = oA + 8u * PITCH_B;
                *(uint32_t*)(smem_raw + A_HI + oA) = hi0;
                *(uint32_t*)(smem_raw + A_LO + oA) = lo0;
                *(uint32_t*)(smem_raw + A_HI + oB) = hi1;
                *(uint32_t*)(smem_raw + A_LO + oB) = lo1;
            }
        }
        __syncwarp();

        // ================= layer 2 (W2) =================
        #pragma unroll
        for (int nt = 0; nt < 16; nt++)
            #pragma unroll
            for (int j = 0; j < 4; j++) D[nt][j] = 0.f;

        {
            const char* Ah = smem_raw + A_HI;
            const char* Al = smem_raw + A_LO;
            const char* Bh = smem_raw + W_SM + 2 * IMG_BYTES;
            const char* Bl = smem_raw + W_SM + 3 * IMG_BYTES;
            const int nrow = (t >> 2);
            #pragma unroll
            for (int ks = 0; ks < 8; ks++) {
                const int kb = ks * 32 + qk4;
                uint32_t ah[4], al[4];
                ah[0] = *(const uint32_t*)(Ah + row0 * PITCH_B + kb);
                ah[1] = *(const uint32_t*)(Ah + (row0 + 8) * PITCH_B + kb);
                ah[2] = *(const uint32_t*)(Ah + row0 * PITCH_B + kb + 16);
                ah[3] = *(const uint32_t*)(Ah + (row0 + 8) * PITCH_B + kb + 16);
                al[0] = *(const uint32_t*)(Al + row0 * PITCH_B + kb);
                al[1] = *(const uint32_t*)(Al + (row0 + 8) * PITCH_B + kb);
                al[2] = *(const uint32_t*)(Al + row0 * PITCH_B + kb + 16);
                al[3] = *(const uint32_t*)(Al + (row0 + 8) * PITCH_B + kb + 16);
                #pragma unroll
                for (int nt = 0; nt < 16; nt++) {
                    const int n = nt * 8 + nrow;
                    uint32_t bh[2], bl[2];
                    bh[0] = *(const uint32_t*)(Bh + n * PITCH_B + kb);
                    bh[1] = *(const uint32_t*)(Bh + n * PITCH_B + kb + 16);
                    bl[0] = *(const uint32_t*)(Bl + n * PITCH_B + kb);
                    bl[1] = *(const uint32_t*)(Bl + n * PITCH_B + kb + 16);
                    mma16816(D[nt], ah, bh);
                    mma16816(D[nt], ah, bl);
                    mma16816(D[nt], al, bh);
                }
            }
        }

        // ---- epilogue 2: bias + leaky, delta = h @ W3 + b3 (register dot +
        //      quad shfl reduce), scatter atomics ----
        {
            float a0r1 = 0.f, a1r1 = 0.f, a0r2 = 0.f, a1r2 = 0.f;
            #pragma unroll
            for (int nt = 0; nt < 16; nt++) {
                const int c0 = nt * 8 + (t & 3) * 2;
                float bia = vb2[c0], bib = vb2[c0 + 1];
                float v0 = D[nt][0] + bia, v1 = D[nt][1] + bib;
                float v2 = D[nt][2] + bia, v3 = D[nt][3] + bib;
                v0 = (v0 > 0.f) ? v0 : 0.001f * v0;
                v1 = (v1 > 0.f) ? v1 : 0.001f * v1;
                v2 = (v2 > 0.f) ? v2 : 0.001f * v2;
                v3 = (v3 > 0.f) ? v3 : 0.001f * v3;
                float w00 = sW3[c0 * 2 + 0], w01 = sW3[c0 * 2 + 1];
                float w10 = sW3[c0 * 2 + 2], w11 = sW3[c0 * 2 + 3];
                a0r1 += v0 * w00 + v1 * w10;
                a1r1 += v0 * w01 + v1 * w11;
                a0r2 += v2 * w00 + v3 * w10;
                a1r2 += v2 * w01 + v3 * w11;
            }
            // reduce over the 4 lanes sharing each row (t&3)
            #pragma unroll
            for (int off = 1; off <= 2; off <<= 1) {
                a0r1 += __shfl_xor_sync(0xffffffffu, a0r1, off);
                a1r1 += __shfl_xor_sync(0xffffffffu, a1r1, off);
                a0r2 += __shfl_xor_sync(0xffffffffu, a0r2, off);
                a1r2 += __shfl_xor_sync(0xffffffffu, a1r2, off);
            }
            if ((t & 3) == 0) {
                #pragma unroll
                for (int half = 0; half < 2; half++) {
                    const int row = row0 + half * 8;
                    const float d0 = (half ? a0r2 : a0r1) + vb3[0];
                    const float d1 = (half ? a1r2 : a1r1) + vb3[1];
                    const int lp = row >> 2;
                    const int tt = row & 3;
                    const int p  = pbase + lp;
                    if (p < P) {
                        const int i0 = sprop[lp * 4 + 0];
                        const int i3 = sprop[lp * 4 + 3];
                        float hx = sdh[row * 3 + 0];
                        float hy = sdh[row * 3 + 1];
                        float hz = sdh[row * 3 + 2];
                        float* o0 = out + (size_t)(i0 * TT + tt) * 3;
                        float* o3 = out + (size_t)(i3 * TT + tt) * 3;
                        atomicAdd(o0 + 0, -0.5f * d0 * hx);
                        atomicAdd(o0 + 1, -0.5f * d0 * hy);
                        atomicAdd(o0 + 2, -0.5f * d0 * hz);
                        atomicAdd(o3 + 0,  0.5f * d1 * hx);
                        atomicAdd(o3 + 1,  0.5f * d1 * hy);
                        atomicAdd(o3 + 2,  0.5f * d1 * hz);
                    }
                }
            }
        }
        __syncthreads();   // protect sprop/geometry for next tile
    }
}

// ---------------------------------------------------------------------------
extern "C" void kernel_launch(void* const* d_in, const int* in_sizes, int n_in,
                              void* d_out, int out_size)
{
    const float* coords  = (const float*)d_in[0];
    const void*  propers = d_in[1];
    const float* enc     = (const float*)d_in[2];
    const float* t_arr   = (const float*)d_in[3];
    const float* answer  = (const float*)d_in[4];
    const float* W0      = (const float*)d_in[5];
    const float* b0      = (const float*)d_in[6];
    const float* W1      = (const float*)d_in[7];
    const float* b1      = (const float*)d_in[8];
    const float* W2      = (const float*)d_in[9];
    const float* b2      = (const float*)d_in[10];
    const float* W3      = (const float*)d_in[11];
    const float* b3      = (const float*)d_in[12];
    float*       out     = (float*)d_out;

    const int N = in_sizes[2] / DD;
    const int P = in_sizes[1] / 4;

    // propers dtype detection
    int nwords = in_sizes[1] < 4096 ? in_sizes[1] : 4096;
    detect_idx_kernel<<<1, 256>>>((const int*)propers, nwords);

    // weight images
    prep_B_kernel<<<64, 256>>>(W1, W2);

    // out starts as 'answer'
    cudaMemcpyAsync(out, answer, sizeof(float) * (size_t)in_sizes[4],
                    cudaMemcpyDeviceToDevice, 0);

    // per-atom layer-0 partials
    const size_t smA = (size_t)(DD * DD + 64 * HPAD) * sizeof(float);
    cudaFuncSetAttribute(precompute_E_kernel,
                         cudaFuncAttributeMaxDynamicSharedMemorySize, (int)smA);
    precompute_E_kernel<<<dim3((N + 63) / 64, 4), 256, smA>>>(enc, W0, N);

    // fused main kernel
    cudaFuncSetAttribute(propers_kernel,
                         cudaFuncAttributeMaxDynamicSharedMemorySize, SMEM_TOTAL);
    const int nblocks = (P + 32 * TILES_PER_BLOCK - 1) / (32 * TILES_PER_BLOCK);
    propers_kernel<<<nblocks, 256, SMEM_TOTAL>>>(
        coords, propers, t_arr, W0, b0, b1, b2, W3, b3, out, N, P);
}